// round 15
// baseline (speedup 1.0000x reference)
#include <cuda_runtime.h>

#define BB    32
#define CINN  16
#define COUTT 32
#define HH    14
#define WW    14
#define KK    5
#define OHH   5
#define OWW   5
#define HWSZ  (HH*WW)        // 196
#define IMG   (HWSZ*HWSZ)    // 38416
#define IMG4  (IMG/4)        // 9604
#define NPAIR (COUTT/2)      // 16 channel pairs

#define RED_BLOCKS   ((BB * IMG4 + 255) / 256)           // 1201
#define USUM_ELEMS   (BB * HWSZ)                          // 6272
#define USUM_BLOCKS  ((USUM_ELEMS + 255) / 256)           // 25

// Scratch (global device arrays; no allocations)
__device__ float g_Csum[BB * IMG];                        // 4.9 MB (L2-resident)
__device__ float g_T[(size_t)BB * COUTT * 25 * HWSZ];     // 20.1 MB (L2-resident)
__device__ float g_usum[USUM_ELEMS];                      // 25 KB

// ---- packed f32x2 helpers (Blackwell FFMA2) --------------------------------
__device__ __forceinline__ unsigned long long pack2(float lo, float hi) {
    unsigned long long r;
    asm("mov.b64 %0, {%1, %2};" : "=l"(r) : "f"(lo), "f"(hi));
    return r;
}
__device__ __forceinline__ unsigned long long bcast2(float v) {
    unsigned long long r;
    asm("mov.b64 %0, {%1, %1};" : "=l"(r) : "f"(v));
    return r;
}
__device__ __forceinline__ void fma2(unsigned long long& d,
                                     unsigned long long a,
                                     unsigned long long b) {
    asm("fma.rn.f32x2 %0, %1, %2, %0;" : "+l"(d) : "l"(a), "l"(b));
}
__device__ __forceinline__ void unpack2(unsigned long long v, float& lo, float& hi) {
    asm("mov.b64 {%0, %1}, %2;" : "=f"(lo), "=f"(hi) : "l"(v));
}

// ---------------------------------------------------------------------------
// Kernel 1: blocks [0,1201):  Csum[b,hw2,hw4] = sum_c C[b,c,...]  (78.7 MB)
//           blocks [1201,1226): usum[b,hw]    = sum_c u[b,c,hw]   (0.4 MB)
// ---------------------------------------------------------------------------
__global__ void reduce_c_kernel(const float4* __restrict__ C4,
                                const float* __restrict__ u) {
    if (blockIdx.x < RED_BLOCKS) {
        int idx = blockIdx.x * blockDim.x + threadIdx.x;
        if (idx >= BB * IMG4) return;
        int b = idx / IMG4;
        int j = idx - b * IMG4;
        const float4* p = C4 + (size_t)b * CINN * IMG4 + j;
        float ax = 0.f, ay = 0.f, az = 0.f, aw = 0.f;
#pragma unroll
        for (int c = 0; c < CINN; c++) {
            float4 v = __ldcs(p + (size_t)c * IMG4);   // streaming: evict-first
            ax += v.x; ay += v.y; az += v.z; aw += v.w;
        }
        reinterpret_cast<float4*>(g_Csum)[idx] = make_float4(ax, ay, az, aw);
    } else {
        int t = (blockIdx.x - RED_BLOCKS) * blockDim.x + threadIdx.x;
        if (t >= USUM_ELEMS) return;
        int b  = t / HWSZ;
        int hw = t - b * HWSZ;
        const float* up = u + (size_t)b * CINN * HWSZ + hw;
        float a = 0.f;
#pragma unroll
        for (int c = 0; c < CINN; c++) a += up[c * HWSZ];
        g_usum[t] = a;
    }
}

// ---------------------------------------------------------------------------
// Kernel 2: FIRST conv now over dims (2,3) — reduction runs over ROWS of
// Csum so tid indexes the contiguous hw4 dim: all loads 128B-coalesced.
// T[b][i][q][hw4] = sum_{r,c} w[i,rc] * Csum[b][(2y2+r)*14+(2x2+c)][hw4]
// grid = (25 q-positions, B), block = 224 (tid<196 active). FFMA2 pairs.
// ---------------------------------------------------------------------------
__global__ void conv1_kernel(const float* __restrict__ w) {
    __shared__ unsigned long long ws2[25 * NPAIR];   // [k][ipair]
    int tid = threadIdx.x;

    for (int t = tid; t < 25 * NPAIR; t += blockDim.x) {
        int k  = t / NPAIR;
        int ip = t - k * NPAIR;
        ws2[t] = pack2(w[(2 * ip) * 25 + k], w[(2 * ip + 1) * 25 + k]);
    }
    __syncthreads();

    int q  = blockIdx.x;              // q = y2*5+x2
    int b  = blockIdx.y;
    int y2 = q / OWW, x2 = q - y2 * OWW;

    if (tid < HWSZ) {
        // row base (h2,w2) = (2*y2, 2*x2); row step r: +14 rows, c: +1 row
        const float* src = g_Csum + (size_t)b * IMG
                           + ((2 * y2) * WW + 2 * x2) * HWSZ + tid;
        unsigned long long patch2[25];
#pragma unroll
        for (int r = 0; r < KK; r++)
#pragma unroll
            for (int c = 0; c < KK; c++)
                patch2[r * KK + c] = bcast2(__ldg(src + (r * WW + c) * HWSZ));

        float* dst = g_T + (((size_t)b * COUTT) * 25 + q) * HWSZ + tid;
#pragma unroll
        for (int ip = 0; ip < NPAIR; ip++) {
            unsigned long long acc = 0ull;
#pragma unroll
            for (int k = 0; k < 25; k++)
                fma2(acc, patch2[k], ws2[k * NPAIR + ip]);
            float lo, hi;
            unpack2(acc, lo, hi);
            dst[(size_t)(2 * ip)     * 25 * HWSZ] = lo;   // coalesced over tid
            dst[(size_t)(2 * ip + 1) * 25 * HWSZ] = hi;
        }
    }
}

// ---------------------------------------------------------------------------
// Kernel 3: SECOND conv over dims (4,5) + fused mean path.
// out_cov[b,i,q,p] = sum_{r,c} w[i,rc] * T[b,i,q,(2y1+r)*14+(2x1+c)]
// out_mean[b,i,y,x] = sum_a w[i,a] * usum[b, win_{y,x}(a)]
// grid = B*COUT, block = 640 (tid<625 cov, tid<25 also mean)
// ---------------------------------------------------------------------------
__global__ void conv2_kernel(const float* __restrict__ w,
                             float* __restrict__ out_cov,
                             float* __restrict__ out_mean) {
    __shared__ float Ts[25 * HWSZ];   // 4900 floats = 19.6 KB
    __shared__ float ws[25];
    __shared__ float us[HWSZ];
    int tid = threadIdx.x;
    int bi  = blockIdx.x;             // b*32 + i
    int i   = bi % COUTT;
    int b   = bi / COUTT;

    const float* tsrc = g_T + (size_t)bi * 25 * HWSZ;
    for (int k = tid; k < 25 * HWSZ; k += blockDim.x) Ts[k] = tsrc[k];
    if (tid < 25) ws[tid] = w[i * 25 + tid];
    if (tid >= 32 && tid < 32 + HWSZ) us[tid - 32] = g_usum[b * HWSZ + (tid - 32)];
    __syncthreads();

    if (tid < 625) {
        int q = tid / 25;             // y2*5+x2 (from conv1)
        int p = tid - q * 25;         // y1*5+x1 (this conv)
        int y1 = p / OWW, x1 = p - y1 * OWW;
        const float* base = Ts + q * HWSZ + (2 * y1) * WW + 2 * x1;
        float acc = 0.f;
#pragma unroll
        for (int r = 0; r < KK; r++)
#pragma unroll
            for (int c = 0; c < KK; c++)
                acc += ws[r * KK + c] * base[r * WW + c];
        out_cov[(size_t)bi * 625 + tid] = acc;   // [b,i,y2,x2,y1,x1] coalesced
    }

    if (tid < 25) {                   // mean outputs for this (b,i)
        int y = tid / OWW, x = tid - y * OWW;
        const float* base = us + (2 * y) * WW + 2 * x;
        float acc = 0.f;
#pragma unroll
        for (int r = 0; r < KK; r++)
#pragma unroll
            for (int c = 0; c < KK; c++)
                acc += ws[r * KK + c] * base[r * WW + c];
        out_mean[(size_t)bi * 25 + tid] = acc;
    }
}

// ---------------------------------------------------------------------------
extern "C" void kernel_launch(void* const* d_in, const int* in_sizes, int n_in,
                              void* d_out, int out_size) {
    const float* u = (const float*)d_in[0];   // [32,16,14,14]
    const float* C = (const float*)d_in[1];   // [32,16,14,14,14,14]
    const float* w = (const float*)d_in[2];   // [32,1,5,5]
    float* out      = (float*)d_out;
    float* out_mean = out;                               // 25600 floats
    float* out_cov  = out + BB * COUTT * OHH * OWW;      // 640000 floats

    // 1) channel reductions (C: HBM-bound; u: appended blocks)
    reduce_c_kernel<<<RED_BLOCKS + USUM_BLOCKS, 256>>>((const float4*)C, u);

    // 2) first conv over dims (2,3) — coalesced against native Csum layout
    dim3 g1(25, BB);
    conv1_kernel<<<g1, 224>>>(w);

    // 3) second conv over dims (4,5) + fused mean path
    conv2_kernel<<<BB * COUTT, 640>>>(w, out_cov, out_mean);
}

// round 16
// speedup vs baseline: 1.2273x; 1.2273x over previous
#include <cuda_runtime.h>

#define BB    32
#define CINN  16
#define COUTT 32
#define HH    14
#define WW    14
#define KK    5
#define OHH   5
#define OWW   5
#define HWSZ  (HH*WW)        // 196
#define IMG   (HWSZ*HWSZ)    // 38416
#define IMG4  (IMG/4)        // 9604
#define NPAIR (COUTT/2)      // 16

#define RED_BLOCKS   ((BB * IMG4 + 255) / 256)           // 1201
#define USUM_ELEMS   (BB * HWSZ)                          // 6272
#define USUM_BLOCKS  ((USUM_ELEMS + 255) / 256)           // 25

// Scratch (global device arrays; no allocations)
__device__ float g_Csum[BB * IMG];                        // 4.9 MB (L2-resident)
__device__ float g_usum[USUM_ELEMS];                      // 25 KB

// ---- packed f32x2 helpers (Blackwell FFMA2) --------------------------------
__device__ __forceinline__ unsigned long long bcast2(float v) {
    unsigned long long r;
    asm("mov.b64 %0, {%1, %1};" : "=l"(r) : "f"(v));
    return r;
}
__device__ __forceinline__ void fma2(unsigned long long& d,
                                     unsigned long long a,
                                     unsigned long long b) {
    asm("fma.rn.f32x2 %0, %1, %2, %0;" : "+l"(d) : "l"(a), "l"(b));
}
__device__ __forceinline__ void unpack2(unsigned long long v, float& lo, float& hi) {
    asm("mov.b64 {%0, %1}, %2;" : "=f"(lo), "=f"(hi) : "l"(v));
}

// ---------------------------------------------------------------------------
// Kernel 1: blocks [0,1201):  Csum[b,hw2,hw4] = sum_c C[b,c,...]  (78.7 MB)
//           blocks [1201,1226): usum[b,hw]    = sum_c u[b,c,hw]
// ---------------------------------------------------------------------------
__global__ void reduce_c_kernel(const float4* __restrict__ C4,
                                const float* __restrict__ u) {
    if (blockIdx.x < RED_BLOCKS) {
        int idx = blockIdx.x * blockDim.x + threadIdx.x;
        if (idx >= BB * IMG4) return;
        int b = idx / IMG4;
        int j = idx - b * IMG4;
        const float4* p = C4 + (size_t)b * CINN * IMG4 + j;
        float ax = 0.f, ay = 0.f, az = 0.f, aw = 0.f;
#pragma unroll
        for (int c = 0; c < CINN; c++) {
            float4 v = __ldcs(p + (size_t)c * IMG4);   // streaming: evict-first
            ax += v.x; ay += v.y; az += v.z; aw += v.w;
        }
        reinterpret_cast<float4*>(g_Csum)[idx] = make_float4(ax, ay, az, aw);
    } else {
        int t = (blockIdx.x - RED_BLOCKS) * blockDim.x + threadIdx.x;
        if (t >= USUM_ELEMS) return;
        int b  = t / HWSZ;
        int hw = t - b * HWSZ;
        const float* up = u + (size_t)b * CINN * HWSZ + hw;
        float a = 0.f;
#pragma unroll
        for (int c = 0; c < CINN; c++) a += up[c * HWSZ];
        g_usum[t] = a;
    }
}

// ---------------------------------------------------------------------------
// Kernel 2 (fully fused): block = (q = y2*5+x2, b).  No global intermediate.
//  Stage L: Rs[k][j] = Csum[b][(2y2+k/5)*14 + 2x2+k%5][j]   (25 rows, 19.6 KB)
//  Stage A: Ts[i][j] = sum_k w[i,k] * Rs[k][j]              (FFMA2 pairs)
//  Stage B: out_cov[b,i,q,p] = sum_a w[i,a] * Ts[i][win_p(a)]
//  Mean   : out_mean[b,i,q]  = sum_a w[i,a] * usum[b][win_q(a)]
// ---------------------------------------------------------------------------
__global__ void conv_fused_kernel(const float* __restrict__ w,
                                  float* __restrict__ out_cov,
                                  float* __restrict__ out_mean) {
    __shared__ float Rs[25 * HWSZ];                 // 19,600 B
    __shared__ float Ts[COUTT * HWSZ];              // 25,088 B
    __shared__ __align__(16) float wsf[25 * COUTT]; //  3,200 B  [k][i]
    __shared__ float us[HWSZ];                      //    784 B

    const int tid = threadIdx.x;
    const int q   = blockIdx.x;         // y2*5+x2
    const int b   = blockIdx.y;
    const int y2  = q / OWW, x2 = q - y2 * OWW;

    // weights, k-major: wsf[k*32+i] = w[i*25+k]
    for (int t = tid; t < 25 * COUTT; t += blockDim.x) {
        int k = t >> 5, i = t & 31;
        wsf[t] = __ldg(w + i * 25 + k);
    }
    if (tid < HWSZ) us[tid] = g_usum[b * HWSZ + tid];

    // Stage L: 25 needed Csum rows, coalesced
    {
        const float* src = g_Csum + (size_t)b * IMG;
        for (int t = tid; t < 25 * HWSZ; t += blockDim.x) {
            int k = t / HWSZ, j = t - k * HWSZ;
            int row = (2 * y2 + k / KK) * WW + (2 * x2 + k % KK);
            Rs[t] = __ldg(src + (size_t)row * HWSZ + j);
        }
    }
    __syncthreads();

    // Stage A: first conv (dims 2,3) -> Ts in smem, channels in FFMA2 pairs
    if (tid < HWSZ) {
        unsigned long long p2[25];
#pragma unroll
        for (int k = 0; k < 25; k++) p2[k] = bcast2(Rs[k * HWSZ + tid]);

#pragma unroll
        for (int ip = 0; ip < NPAIR; ip++) {
            unsigned long long acc = 0ull;
#pragma unroll
            for (int k = 0; k < 25; k++) {
                unsigned long long wv =
                    *reinterpret_cast<const unsigned long long*>(wsf + k * COUTT + 2 * ip);
                fma2(acc, p2[k], wv);
            }
            float lo, hi;
            unpack2(acc, lo, hi);
            Ts[(2 * ip)     * HWSZ + tid] = lo;
            Ts[(2 * ip + 1) * HWSZ + tid] = hi;
        }
    }
    __syncthreads();

    // Stage B: second conv (dims 4,5) -> 800 cov outputs for this (b,q)
    for (int o = tid; o < COUTT * 25; o += blockDim.x) {
        int i = o / 25, p = o - i * 25;
        int y1 = p / OWW, x1 = p - y1 * OWW;
        const float* base = Ts + i * HWSZ + (2 * y1) * WW + 2 * x1;
        float acc = 0.f;
#pragma unroll
        for (int r = 0; r < KK; r++)
#pragma unroll
            for (int c = 0; c < KK; c++)
                acc += wsf[(r * KK + c) * COUTT + i] * base[r * WW + c];
        out_cov[((size_t)(b * COUTT + i)) * 625 + q * 25 + p] = acc;
    }

    // Mean: 32 outputs for this (b, q)
    if (tid < COUTT) {
        const float* base = us + (2 * y2) * WW + 2 * x2;
        float acc = 0.f;
#pragma unroll
        for (int r = 0; r < KK; r++)
#pragma unroll
            for (int c = 0; c < KK; c++)
                acc += wsf[(r * KK + c) * COUTT + tid] * base[r * WW + c];
        out_mean[((size_t)(b * COUTT + tid)) * 25 + q] = acc;
    }
}

// ---------------------------------------------------------------------------
extern "C" void kernel_launch(void* const* d_in, const int* in_sizes, int n_in,
                              void* d_out, int out_size) {
    const float* u = (const float*)d_in[0];   // [32,16,14,14]
    const float* C = (const float*)d_in[1];   // [32,16,14,14,14,14]
    const float* w = (const float*)d_in[2];   // [32,1,5,5]
    float* out      = (float*)d_out;
    float* out_mean = out;                               // 25600 floats
    float* out_cov  = out + BB * COUTT * OHH * OWW;      // 640000 floats

    // 1) channel reductions (C: HBM-bound; u: appended blocks)
    reduce_c_kernel<<<RED_BLOCKS + USUM_BLOCKS, 256>>>((const float4*)C, u);

    // 2) fully fused double conv + mean (no global intermediate)
    dim3 g2(25, BB);
    conv_fused_kernel<<<g2, 224>>>(w, out_cov, out_mean);
}

// round 17
// speedup vs baseline: 1.5301x; 1.2468x over previous
#include <cuda_runtime.h>

#define BB    32
#define CINN  16
#define COUTT 32
#define HH    14
#define WW    14
#define KK    5
#define OHH   5
#define OWW   5
#define HWSZ  (HH*WW)        // 196
#define IMG   (HWSZ*HWSZ)    // 38416
#define IMG4  (IMG/4)        // 9604
#define NPAIR (COUTT/2)      // 16
#define TSW   169            // 13x13 positions stage B reads

#define RED_BLOCKS   ((BB * IMG4 + 255) / 256)           // 1201
#define USUM_ELEMS   (BB * HWSZ)                          // 6272
#define USUM_BLOCKS  ((USUM_ELEMS + 255) / 256)           // 25

// Scratch (global device arrays; no allocations)
__device__ float g_Csum[BB * IMG];                        // 4.9 MB (L2-resident)
__device__ float g_usum[USUM_ELEMS];                      // 25 KB

// ---- packed f32x2 helpers (Blackwell FFMA2) --------------------------------
__device__ __forceinline__ unsigned long long bcast2(float v) {
    unsigned long long r;
    asm("mov.b64 %0, {%1, %1};" : "=l"(r) : "f"(v));
    return r;
}
__device__ __forceinline__ void fma2(unsigned long long& d,
                                     unsigned long long a,
                                     unsigned long long b) {
    asm("fma.rn.f32x2 %0, %1, %2, %0;" : "+l"(d) : "l"(a), "l"(b));
}
__device__ __forceinline__ void unpack2(unsigned long long v, float& lo, float& hi) {
    asm("mov.b64 {%0, %1}, %2;" : "=f"(lo), "=f"(hi) : "l"(v));
}

// ---------------------------------------------------------------------------
// Kernel 1: blocks [0,1201):  Csum[b,hw2,hw4] = sum_c C[b,c,...]  (78.7 MB)
//           blocks [1201,1226): usum[b,hw]    = sum_c u[b,c,hw]
// ---------------------------------------------------------------------------
__global__ void reduce_c_kernel(const float4* __restrict__ C4,
                                const float* __restrict__ u) {
    if (blockIdx.x < RED_BLOCKS) {
        int idx = blockIdx.x * blockDim.x + threadIdx.x;
        if (idx >= BB * IMG4) return;
        int b = idx / IMG4;
        int j = idx - b * IMG4;
        const float4* p = C4 + (size_t)b * CINN * IMG4 + j;
        float ax = 0.f, ay = 0.f, az = 0.f, aw = 0.f;
#pragma unroll
        for (int c = 0; c < CINN; c++) {
            float4 v = __ldcs(p + (size_t)c * IMG4);   // streaming: evict-first
            ax += v.x; ay += v.y; az += v.z; aw += v.w;
        }
        reinterpret_cast<float4*>(g_Csum)[idx] = make_float4(ax, ay, az, aw);
    } else {
        int t = (blockIdx.x - RED_BLOCKS) * blockDim.x + threadIdx.x;
        if (t >= USUM_ELEMS) return;
        int b  = t / HWSZ;
        int hw = t - b * HWSZ;
        const float* up = u + (size_t)b * CINN * HWSZ + hw;
        float a = 0.f;
#pragma unroll
        for (int c = 0; c < CINN; c++) a += up[c * HWSZ];
        g_usum[t] = a;
    }
}

// ---------------------------------------------------------------------------
// Kernel 2 (fully fused): block = (q = y2*5+x2, b).  No global intermediate.
//  Stage L: Rs[k][j] = Csum[b][row_q(k)][j]           (25 coalesced rows)
//  Stage A: Ts[i][jj] = sum_k w[i,k] * Rs[k][j(jj)]   (k outer, 16 acc ILP)
//  Mean   : on threads 169..200, overlapped with stage A
//  Stage B: out_cov[b,i,q,p] = sum_a w[i,a] * Ts[i][win_p(a)]
// ---------------------------------------------------------------------------
__global__ void __launch_bounds__(224, 5)
conv_fused_kernel(const float* __restrict__ w,
                  float* __restrict__ out_cov,
                  float* __restrict__ out_mean) {
    __shared__ float Rs[25 * HWSZ];                 // 19,600 B
    __shared__ float Ts[COUTT * TSW];               // 21,632 B
    __shared__ __align__(16) float wsf[25 * COUTT]; //  3,200 B  [k][i]

    const int tid = threadIdx.x;
    const int q   = blockIdx.x;         // y2*5+x2
    const int b   = blockIdx.y;
    const int y2  = q / OWW, x2 = q - y2 * OWW;
    const int base_row = (2 * y2) * WW + 2 * x2;

    // weights, k-major: wsf[k*32+i] = w[i*25+k]
#pragma unroll
    for (int t = tid; t < 25 * COUTT; t += 224) {
        int k = t >> 5, i = t & 31;
        wsf[t] = __ldg(w + i * 25 + k);
    }

    // Stage L: 25 needed Csum rows, coalesced, k unrolled (no div/mod)
    if (tid < HWSZ) {
        const float* src = g_Csum + (size_t)b * IMG + tid;
#pragma unroll
        for (int k = 0; k < 25; k++) {
            int row = base_row + (k / KK) * WW + (k % KK);   // compile-time parts
            Rs[k * HWSZ + tid] = __ldg(src + (size_t)row * HWSZ);
        }
    }
    __syncthreads();

    if (tid < TSW) {
        // Stage A: k outer, 16 independent FFMA2 accumulators
        const int j = (tid / 13) * WW + (tid % 13);
        unsigned long long acc[NPAIR];
#pragma unroll
        for (int ip = 0; ip < NPAIR; ip++) acc[ip] = 0ull;
#pragma unroll
        for (int k = 0; k < 25; k++) {
            unsigned long long pv = bcast2(Rs[k * HWSZ + j]);
            const unsigned long long* wrow =
                reinterpret_cast<const unsigned long long*>(wsf + k * COUTT);
#pragma unroll
            for (int ip = 0; ip < NPAIR; ip++) fma2(acc[ip], pv, wrow[ip]);
        }
#pragma unroll
        for (int ip = 0; ip < NPAIR; ip++) {
            float lo, hi;
            unpack2(acc[ip], lo, hi);
            Ts[(2 * ip)     * TSW + tid] = lo;
            Ts[(2 * ip + 1) * TSW + tid] = hi;
        }
    } else if (tid < TSW + COUTT) {
        // Mean path on otherwise-idle threads (overlaps stage A)
        const int i = tid - TSW;
        const float* base = g_usum + b * HWSZ + base_row;
        float acc = 0.f;
#pragma unroll
        for (int r = 0; r < KK; r++)
#pragma unroll
            for (int c = 0; c < KK; c++)
                acc += wsf[(r * KK + c) * COUTT + i] * __ldg(base + r * WW + c);
        out_mean[((size_t)(b * COUTT + i)) * 25 + q] = acc;
    }
    __syncthreads();

    // Stage B: second conv (dims 4,5) -> 800 cov outputs for this (b,q)
#pragma unroll
    for (int o = tid; o < COUTT * 25; o += 224) {
        int i = o / 25, p = o - i * 25;
        int y1 = p / OWW, x1 = p - y1 * OWW;
        const float* base = Ts + i * TSW + (2 * y1) * 13 + 2 * x1;
        float acc = 0.f;
#pragma unroll
        for (int r = 0; r < KK; r++)
#pragma unroll
            for (int c = 0; c < KK; c++)
                acc += wsf[(r * KK + c) * COUTT + i] * base[r * 13 + c];
        out_cov[((size_t)(b * COUTT + i)) * 625 + q * 25 + p] = acc;
    }
}

// ---------------------------------------------------------------------------
extern "C" void kernel_launch(void* const* d_in, const int* in_sizes, int n_in,
                              void* d_out, int out_size) {
    const float* u = (const float*)d_in[0];   // [32,16,14,14]
    const float* C = (const float*)d_in[1];   // [32,16,14,14,14,14]
    const float* w = (const float*)d_in[2];   // [32,1,5,5]
    float* out      = (float*)d_out;
    float* out_mean = out;                               // 25600 floats
    float* out_cov  = out + BB * COUTT * OHH * OWW;      // 640000 floats

    // 1) channel reductions (C: HBM-bound; u: appended blocks)
    reduce_c_kernel<<<RED_BLOCKS + USUM_BLOCKS, 256>>>((const float4*)C, u);

    // 2) fully fused double conv + mean (no global intermediate)
    dim3 g2(25, BB);
    conv_fused_kernel<<<g2, 224>>>(w, out_cov, out_mean);
}